// round 14
// baseline (speedup 1.0000x reference)
#include <cuda_runtime.h>

typedef unsigned long long ull;

#define Lg 64
#define Bg 1024
#define TH 16
#define NTILES (Lg/TH)          // 4
#define THREADS 512
#define R1 (TH+4)               // 20 conv1 output rows (halo 2)
#define R2 (TH+2)               // 18 conv2 output rows (halo 1)
#define RZ (TH+6)               // 22 input rows (halo 3)
#define PW 40                   // pairs per row padded: entries 0..39, pair p at p+1
                                // (row stride 40 ull = 16 banks -> 2-rows-per-warp
                                //  act loads are bank-conflict-free)

// ---- shared memory layout (ull units) ----
#define S1U 0                               // 16*20*40 = 12800
#define S2U (S1U + 16*R1*PW)                // 12800 (+16*18*40 = 11520)
#define SZU (S2U + 16*R2*PW)                // 24320 (+22*40 = 880)
#define WS1 (SZU + RZ*PW)                   // 25200: W1 scalar floats (1152 ull)
#define WS0 (WS1 + 1152)                    // 26352: W0 scalar (72 ull)
#define WU2 (WS0 + 72)                      // 26424: W2 packed pairs (144 ull)
#define BFU (WU2 + 144)                     // 26568: packed biases (33 ull)
#define U_TOTAL (BFU + 33)                  // 26601
#define SMEM_BYTES ((size_t)U_TOTAL * 8)    // 212808 B (<= 227KB cap)

// ---- packed f32x2 helpers (sm_100+) : per-lane exact fp32 ops ----
__device__ __forceinline__ ull pk(float lo, float hi) {
    ull r; asm("mov.b64 %0, {%1, %2};" : "=l"(r) : "f"(lo), "f"(hi)); return r;
}
__device__ __forceinline__ void upk(ull v, float& lo, float& hi) {
    asm("mov.b64 {%0, %1}, %2;" : "=f"(lo), "=f"(hi) : "l"(v));
}
__device__ __forceinline__ void fma2(ull& d, ull a, ull b) {   // d += a*b
    asm("fma.rn.f32x2 %0, %1, %2, %0;" : "+l"(d) : "l"(a), "l"(b));
}
__device__ __forceinline__ void fma2h(ull& d, ull a, ull c) {  // d = d*a + c
    asm("fma.rn.f32x2 %0, %0, %1, %2;" : "+l"(d) : "l"(a), "l"(c));
}
__device__ __forceinline__ ull add2(ull a, ull b) {
    ull r; asm("add.rn.f32x2 %0, %1, %2;" : "=l"(r) : "l"(a), "l"(b)); return r;
}
__device__ __forceinline__ ull mul2(ull a, ull b) {
    ull r; asm("mul.rn.f32x2 %0, %1, %2;" : "=l"(r) : "l"(a), "l"(b)); return r;
}
__device__ __forceinline__ ull dup(float f) { return pk(f, f); }
__device__ __forceinline__ ull swap32(ull v) { return (v >> 32) | (v << 32); }

// Packed XLA EmitFastTanh on an accumulator pair + packed bias.
// Per-lane op sequence identical to the verified scalar replica.
// DO NOT CHANGE the op sequence (bit-exactness vs XLA verified).
__device__ __forceinline__ ull xla_tanh2(ull acc, ull bias2) {
    ull s = add2(acc, bias2);
    float s0, s1; upk(s, s0, s1);
    float xc0 = fminf(fmaxf(s0, -9.0f), 9.0f);
    float xc1 = fminf(fmaxf(s1, -9.0f), 9.0f);
    ull xc = pk(xc0, xc1);
    ull x2 = mul2(xc, xc);
    ull p = dup(-2.76076847742355e-16f);
    fma2h(p, x2, dup( 2.00018790482477e-13f));
    fma2h(p, x2, dup(-8.60467152213735e-11f));
    fma2h(p, x2, dup( 5.12229709037114e-08f));
    fma2h(p, x2, dup( 1.48572235717979e-05f));
    fma2h(p, x2, dup( 6.37261928875436e-04f));
    fma2h(p, x2, dup( 4.89352455891786e-03f));
    ull num = mul2(xc, p);
    ull q = dup(1.19825839466702e-06f);
    fma2h(q, x2, dup(1.18534705686654e-04f));
    fma2h(q, x2, dup(2.26843463243900e-03f));
    fma2h(q, x2, dup(4.89352518554385e-03f));
    float n0, n1, q0, q1;
    upk(num, n0, n1); upk(q, q0, q1);
    float r0 = __fdiv_rn(n0, q0);
    float r1 = __fdiv_rn(n1, q1);
    float t0 = (fabsf(s0) < 0.0004f) ? s0 : r0;
    float t1 = (fabsf(s1) < 0.0004f) ? s1 : r1;
    return pk(t0, t1);
}

__global__ void copy_k(const float4* __restrict__ in, float4* __restrict__ out) {
    int i = blockIdx.x * blockDim.x + threadIdx.x;
    out[i] = in[i];
}

// Task decode (phases 1/2), 16 tasks per row: T -> rr = T>>4,
// p0 = (T>>1)&7 (pairs p0, p0+8, p0+16, p0+24), coB = (T&1)*8.
// 4pp x 8co = 32 acc pairs. Per (dy,dx,ci) iter: 4 act LDS.64 (32B) +
// 2 weight float4 (32B) per 32 FMA2 = 2 B/FMA2 through L1tex.
// 32 independent FMA chains per iter -> self-covering ILP per warp.

// conv1 task: chain (dy,dx)
__device__ __forceinline__ void conv1_task(ull* su, int T) {
    int rr = T >> 4;
    int p0 = (T >> 1) & 7;
    int coB = (T & 1) << 3;
    const float* wsf = (const float*)(su + WS0);
    ull acc[32];
    #pragma unroll
    for (int i = 0; i < 32; i++) acc[i] = 0ull;
    #pragma unroll
    for (int dy = 0; dy < 3; dy++) {
        const ull* rp = su + SZU + (rr + dy) * PW + 1;
        #pragma unroll
        for (int dx = 0; dx < 3; dx++) {
            const float* wq = wsf + (dy * 3 + dx) * 16 + coB;
            float4 wa = *(const float4*)(wq);
            float4 wb = *(const float4*)(wq + 4);
            ull w[8];
            w[0] = dup(wa.x); w[1] = dup(wa.y); w[2] = dup(wa.z); w[3] = dup(wa.w);
            w[4] = dup(wb.x); w[5] = dup(wb.y); w[6] = dup(wb.z); w[7] = dup(wb.w);
            #pragma unroll
            for (int k = 0; k < 4; k++) {
                ull q = rp[p0 + 8 * k + dx - 1];
                #pragma unroll
                for (int j = 0; j < 8; j++)
                    fma2(acc[k * 8 + j], w[j], q);
            }
        }
    }
    #pragma unroll
    for (int j = 0; j < 8; j++) {
        int co = coB + j;
        ull b2v = su[BFU + co];
        ull* op = su + S1U + (co * R1 + rr) * PW + 1;
        #pragma unroll
        for (int k = 0; k < 4; k++) {
            ull r = xla_tanh2(acc[k * 8 + j], b2v);
            op[p0 + 8 * k] = r;
            if (k == 3 && p0 == 7) op[-1] = swap32(r);  // halo = swap(pair 31)
            if (k == 0 && p0 == 0) op[32] = swap32(r);  // halo = swap(pair 0)
        }
    }
}

// conv2 task: chain (dy,dx,ci), ci-loop manually pipelined (depth 1)
__device__ __forceinline__ void conv2_task(ull* su, int T) {
    int rr = T >> 4;
    int p0 = (T >> 1) & 7;
    int coB = (T & 1) << 3;
    const float* wsf = (const float*)(su + WS1);
    ull acc[32];
    #pragma unroll
    for (int i = 0; i < 32; i++) acc[i] = 0ull;
    #pragma unroll
    for (int dy = 0; dy < 3; dy++) {
        const ull* rbp = su + S1U + (rr + dy) * PW + 1;
        #pragma unroll
        for (int dx = 0; dx < 3; dx++) {
            const float* wb = wsf + (dy * 3 + dx) * 256 + coB;
            // pipeline prologue: ci = 0
            ull q0v = rbp[p0 + dx - 1];
            ull q1v = rbp[p0 + 8 + dx - 1];
            ull q2v = rbp[p0 + 16 + dx - 1];
            ull q3v = rbp[p0 + 24 + dx - 1];
            float4 wva = *(const float4*)(wb);
            float4 wvb = *(const float4*)(wb + 4);
            #pragma unroll
            for (int ci = 0; ci < 16; ci++) {
                ull n0 = q0v, n1 = q1v, n2 = q2v, n3 = q3v;
                float4 nwa = wva, nwb = wvb;
                if (ci < 15) {                      // prefetch ci+1
                    const ull* rp = rbp + (ci + 1) * (R1 * PW);
                    n0 = rp[p0 + dx - 1];
                    n1 = rp[p0 + 8 + dx - 1];
                    n2 = rp[p0 + 16 + dx - 1];
                    n3 = rp[p0 + 24 + dx - 1];
                    nwa = *(const float4*)(wb + (ci + 1) * 16);
                    nwb = *(const float4*)(wb + (ci + 1) * 16 + 4);
                }
                ull w[8];
                w[0] = dup(wva.x); w[1] = dup(wva.y); w[2] = dup(wva.z); w[3] = dup(wva.w);
                w[4] = dup(wvb.x); w[5] = dup(wvb.y); w[6] = dup(wvb.z); w[7] = dup(wvb.w);
                #pragma unroll
                for (int j = 0; j < 8; j++) {
                    fma2(acc[0  + j], w[j], q0v);
                    fma2(acc[8  + j], w[j], q1v);
                    fma2(acc[16 + j], w[j], q2v);
                    fma2(acc[24 + j], w[j], q3v);
                }
                q0v = n0; q1v = n1; q2v = n2; q3v = n3;
                wva = nwa; wvb = nwb;
            }
        }
    }
    #pragma unroll
    for (int j = 0; j < 8; j++) {
        int co = coB + j;
        ull b2v = su[BFU + 16 + co];
        ull* op = su + S2U + (co * R2 + rr) * PW + 1;
        #pragma unroll
        for (int k = 0; k < 4; k++) {
            ull r = xla_tanh2(acc[k * 8 + j], b2v);
            op[p0 + 8 * k] = r;
            if (k == 3 && p0 == 7) op[-1] = swap32(r);
            if (k == 0 && p0 == 0) op[32] = swap32(r);
        }
    }
}

// One fused layer. All conv accumulations are single fp32 FMA chains from 0
// in k = (dy, dx, ci) order (ci fastest), bias after — bit-identical to XLA.
__global__ void __launch_bounds__(THREADS, 1)
layer_kernel(float* __restrict__ x,
             const float* __restrict__ w0, const float* __restrict__ b0,
             const float* __restrict__ w1, const float* __restrict__ b1,
             const float* __restrict__ w2, const float* __restrict__ b2,
             int parity)
{
    extern __shared__ ull su[];

    const int tid   = threadIdx.x;
    const int rbase = blockIdx.x * TH;                 // even
    const int xbase = ((int)blockIdx.y) << 12;         // b*4096

    // ---- Phase 0: scalar weights (conv1/conv2), packed W2 + biases, input ----
    {
        float* ws1 = (float*)(su + WS1);
        for (int t = tid; t < 2304; t += THREADS) ws1[t] = w1[t];
    }
    if (tid < 144) {
        ((float*)(su + WS0))[tid] = w0[tid];
        float b = w2[tid];
        su[WU2 + tid] = pk(b, b);
    }
    if (tid >= 160 && tid < 176) { int i = tid - 160; float v = b0[i]; su[BFU + i] = pk(v, v); }
    if (tid >= 192 && tid < 208) { int i = tid - 192; float v = b1[i]; su[BFU + 16 + i] = pk(v, v); }
    if (tid == 224) { float v = b2[0]; su[BFU + 32] = pk(v, v); }

    // packed masked input: entry e (0..33) of row rr holds pair p = e-1:
    // ( z[gr][p&63], z[gr][(p+32)&63] ), zeroed at non-A sites.
    for (int t = tid; t < RZ * 34; t += THREADS) {
        int rr = t / 34, e = t - rr * 34, p = e - 1;
        int gr = (rbase + rr - 3) & 63;
        int c0 = p & 63, c1 = (p + 32) & 63;
        const float* row = x + xbase + (gr << 6);
        float v0 = row[c0], v1 = row[c1];
        v0 = (((gr + c0) & 1) == parity) ? v0 : 0.0f;
        v1 = (((gr + c1) & 1) == parity) ? v1 : 0.0f;
        su[SZU + rr * PW + e] = pk(v0, v1);
    }
    __syncthreads();

    // ---- Phase 1: conv1 (1 -> 16): 320 tasks (20 rows x 8 pQ x 2 coH) ----
    if (tid < 320) conv1_task(su, tid);
    __syncthreads();

    // ---- Phase 2: conv2 (16 -> 16): 288 tasks (18 rows x 8 pQ x 2 coH) ----
    if (tid < 288) conv2_task(su, tid);
    __syncthreads();

    // ---- Phase 3: conv3 (16 -> 1), chain (dy,dx,ci), bias, STE sign update ----
    // 512 tasks: 16 rows x 32 pairs; pair p0 covers columns (p0, p0+32)
    {
        int rr = tid >> 5;
        int p0 = tid & 31;
        ull acc = 0ull;
        #pragma unroll
        for (int dy = 0; dy < 3; dy++) {
            const ull* rbp = su + S2U + (rr + dy) * PW + 1;
            #pragma unroll
            for (int dx = 0; dx < 3; dx++) {
                const ull* wp = su + WU2 + (dy * 3 + dx) * 16;
                // manual 1-deep pipeline
                ull qa = rbp[p0 + dx - 1];
                ull wv = wp[0];
                #pragma unroll
                for (int ci = 0; ci < 16; ci++) {
                    ull nqa = qa, nwv = wv;
                    if (ci < 15) {
                        nqa = rbp[(ci + 1) * (R2 * PW) + p0 + dx - 1];
                        nwv = wp[ci + 1];
                    }
                    fma2(acc, wv, qa);
                    qa = nqa; wv = nwv;
                }
            }
        }
        float bb, dummy;
        upk(su[BFU + 32], bb, dummy);
        float u0, u1;
        upk(acc, u0, u1);
        float l0 = __fadd_rn(u0, bb);
        float l1 = __fadd_rn(u1, bb);
        int gr = rbase + rr;
        // columns p0 and p0+32 share parity -> uniform condition per thread
        if (((gr + p0) & 1) != parity) {
            float* row = x + xbase + (gr << 6);
            float s0 = (l0 > 0.0f) ? 1.0f : ((l0 < 0.0f) ? -1.0f : 0.0f);
            float s1v = (l1 > 0.0f) ? 1.0f : ((l1 < 0.0f) ? -1.0f : 0.0f);
            // STE forward exactly as XLA computes it: l + (sign(l) - l)
            float m0 = __fadd_rn(l0, __fadd_rn(s0, -l0));
            float m1 = __fadd_rn(l1, __fadd_rn(s1v, -l1));
            row[p0]      = __fmul_rn(row[p0],      m0);
            row[p0 + 32] = __fmul_rn(row[p0 + 32], m1);
        }
    }
}

extern "C" void kernel_launch(void* const* d_in, const int* in_sizes, int n_in,
                              void* d_out, int out_size)
{
    const float* z  = (const float*)d_in[0];
    const float* W0 = (const float*)d_in[1];
    const float* b0 = (const float*)d_in[2];
    const float* W1 = (const float*)d_in[3];
    const float* b1 = (const float*)d_in[4];
    const float* W2 = (const float*)d_in[5];
    const float* b2 = (const float*)d_in[6];
    float* x = (float*)d_out;

    cudaFuncSetAttribute(layer_kernel, cudaFuncAttributeMaxDynamicSharedMemorySize,
                         (int)SMEM_BYTES);

    // reset working state each replay: x <- z
    copy_k<<<(Bg * Lg * Lg) / (4 * 256), 256>>>((const float4*)z, (float4*)x);

    for (int i = 0; i < 4; i++) {
        layer_kernel<<<dim3(NTILES, Bg), THREADS, SMEM_BYTES>>>(
            x,
            W0 + i * 144, b0 + i * 16,
            W1 + i * 2304, b1 + i * 16,
            W2 + i * 144, b2 + i,
            i & 1);
    }
}